// round 7
// baseline (speedup 1.0000x reference)
#include <cuda_runtime.h>
#include <cuda_fp16.h>

// Problem constants
#define B      8
#define C_IN   16
#define H      128
#define W      128
#define KSIZE  3
#define HO     126
#define WO     126
#define NK     128

#define TILE   32
#define NTHREADS 1024

// Weights fp16, layout [k][t][c]: half index = k*152 + t*16 + c
// per-k stride = 304 B = 19 quads (odd -> random k spreads over 8 bank-quads)
#define WKH     152
#define W_BYTES (NK * WKH * 2)               // 38912

// Data fp16, layout [y][x][c]: half index = (ry*34+rx)*24 + c
// pixel record = 16 halves (32B = 2 quads), stride 24 halves = 48 B = 3 quads
#define DROWS   (TILE + KSIZE - 1)           // 34
#define DRECH   24
#define D_BYTES (DROWS * DROWS * DRECH * 2)  // 55488
#define D_OFF   W_BYTES                      // 16B-aligned

#define SMEM_BYTES (W_BYTES + D_BYTES)       // 94400

__global__ __launch_bounds__(NTHREADS, 1)
void kernel_lookup_kernel(const float* __restrict__ data,
                          const int* __restrict__ kernel_idx,
                          const float* __restrict__ weights,
                          float* __restrict__ out)
{
    extern __shared__ __align__(16) char smem[];
    __half* wsm = reinterpret_cast<__half*>(smem);          // [k][t][c]
    __half* dsm = reinterpret_cast<__half*>(smem + D_OFF);  // [p][c]

    const int tid = threadIdx.x;
    const int b   = blockIdx.z;
    const int ty0 = blockIdx.y * TILE;
    const int tx0 = blockIdx.x * TILE;

    // Pixel coords; kidx LDG early so it overlaps staging
    const int tx = tid & 31;
    const int ty = tid >> 5;
    const int oy = ty0 + ty;
    const int ox = tx0 + tx;
    const bool valid = (oy < HO) && (ox < WO);

    int k = 0;
    if (valid) k = kernel_idx[((size_t)b * HO + oy) * WO + ox];

    // ---- stage weights: task = (k,c); read 9 consecutive floats, scatter 9 halves ----
    #pragma unroll 1
    for (int p = tid; p < NK * C_IN; p += NTHREADS) {       // 2048 tasks
        int kk = p >> 4;
        int c  = p & 15;
        const float* w = weights + kk * 144 + c * 9;
        #pragma unroll
        for (int t = 0; t < 9; ++t)
            wsm[kk * WKH + t * 16 + c] = __float2half_rn(w[t]);
    }

    // ---- stage data: task = (c, ry); coalesced row read, scattered half stores ----
    {
        const float* dimg = data + (size_t)b * C_IN * H * W;
        #pragma unroll 1
        for (int task = tid; task < C_IN * DROWS; task += NTHREADS) {   // 544
            int c  = task / DROWS;
            int ry = task - c * DROWS;
            int gy = ty0 + ry;
            float row[DROWS];
            if (gy < H) {
                const float4* s4 = reinterpret_cast<const float4*>(dimg + (c * H + gy) * W + tx0);
                #pragma unroll
                for (int j = 0; j < 8; ++j) {
                    float4 v = s4[j];
                    row[j * 4 + 0] = v.x; row[j * 4 + 1] = v.y;
                    row[j * 4 + 2] = v.z; row[j * 4 + 3] = v.w;
                }
                if (tx0 + 33 < W) {
                    const float* s = dimg + (c * H + gy) * W + tx0;
                    row[32] = s[32]; row[33] = s[33];
                } else { row[32] = 0.0f; row[33] = 0.0f; }
            } else {
                #pragma unroll
                for (int j = 0; j < DROWS; ++j) row[j] = 0.0f;
            }
            __half* drow = dsm + ry * DROWS * DRECH + c;    // + rx*DRECH
            #pragma unroll
            for (int rx = 0; rx < DROWS; ++rx)
                drow[rx * DRECH] = __float2half_rn(row[rx]);
        }
    }

    __syncthreads();

    // ---- compute: 1 px/thread; per tap 2 LDS.128 weights + 2 LDS.128 data ----
    const uint4* wq = reinterpret_cast<const uint4*>(smem + k * (WKH * 2)); // 19 quads/k
    const char*  dbase = reinterpret_cast<const char*>(dsm) + (ty * DROWS + tx) * (DRECH * 2);

    float acc0 = 0.f, acc1 = 0.f, acc2 = 0.f;

    #pragma unroll
    for (int t = 0; t < 9; ++t) {
        const int dy = t / 3;
        const int dx = t - dy * 3;
        const uint4* dq = reinterpret_cast<const uint4*>(dbase + (dy * DROWS + dx) * (DRECH * 2));
        uint4 wA = wq[t * 2];
        uint4 wB = wq[t * 2 + 1];
        uint4 dA = dq[0];
        uint4 dB = dq[1];

        const unsigned* wa = &wA.x;
        const unsigned* da = &dA.x;
        #pragma unroll
        for (int j = 0; j < 4; ++j) {
            float2 wf = __half22float2(*reinterpret_cast<const __half2*>(&wa[j]));
            float2 df = __half22float2(*reinterpret_cast<const __half2*>(&da[j]));
            acc0 = fmaf(wf.x, df.x, acc0);
            acc1 = fmaf(wf.y, df.y, acc1);
        }
        const unsigned* wb = &wB.x;
        const unsigned* db = &dB.x;
        #pragma unroll
        for (int j = 0; j < 4; ++j) {
            float2 wf = __half22float2(*reinterpret_cast<const __half2*>(&wb[j]));
            float2 df = __half22float2(*reinterpret_cast<const __half2*>(&db[j]));
            acc2 = fmaf(wf.x, df.x, acc2);
            acc0 = fmaf(wf.y, df.y, acc0);
        }
    }

    if (valid)
        out[((size_t)b * HO + oy) * WO + ox] = acc0 + acc1 + acc2;
}

extern "C" void kernel_launch(void* const* d_in, const int* in_sizes, int n_in,
                              void* d_out, int out_size)
{
    const float* data = (const float*)d_in[0];
    const int*   kidx = (const int*)d_in[1];
    const float* wts  = (const float*)d_in[2];
    float*       outp = (float*)d_out;

    cudaFuncSetAttribute(kernel_lookup_kernel,
                         cudaFuncAttributeMaxDynamicSharedMemorySize,
                         SMEM_BYTES);

    dim3 grid((WO + TILE - 1) / TILE, (HO + TILE - 1) / TILE, B);  // 4 x 4 x 8
    kernel_lookup_kernel<<<grid, NTHREADS, SMEM_BYTES>>>(data, kidx, wts, outp);
}